// round 5
// baseline (speedup 1.0000x reference)
#include <cuda_runtime.h>
#include <cuda_bf16.h>

#define NUM_VERTS 6890
#define NUM_FACES 13776
#define HH 1024
#define WW 1024
#define NB 16
#define HW (HH * WW)

// Element counts (pairwise distinct) used to identify inputs regardless of order.
#define SZ_VERTS  (16 * NUM_VERTS * 3)   // 330720  f32
#define SZ_FACES  (NUM_FACES * 3)        // 41328   int
#define SZ_PIX    (HW)                   // 1048576 int
#define SZ_BARY   (HW * 3)               // 3145728 f32

// Precomputed face-vertex attributes: [face*3 + k] -> (x, y, z, pad).
// 13776 * 3 * 16B = 661 KB, L2-resident during the main kernel.
__device__ float4 g_face_attr[NUM_FACES * 3];
// Dtype flags discovered on-device (1 = int64, 0 = int32). Deterministic.
__device__ int g_faces_i64;
__device__ int g_pix_i64;

// ---------------------------------------------------------------------------
// Probe: decide whether index buffers are int64 or int32.
// If int32 data is misread as int64, each value is lo + hi*2^32 with random
// hi in [0, NUM_VERTS/NUM_FACES) -> astronomically out of range within a few
// samples. Reads only 512 B, safe under either interpretation.
// ---------------------------------------------------------------------------
__global__ void uvr_probe(const void* __restrict__ faces,
                          const void* __restrict__ pix) {
    if (threadIdx.x != 0 || blockIdx.x != 0) return;
    const long long* f64 = (const long long*)faces;
    int ok_f = 1;
    for (int i = 0; i < 64; i++) {
        long long v = f64[i];
        if (v < 0 || v >= NUM_VERTS) { ok_f = 0; break; }
    }
    g_faces_i64 = ok_f;

    const long long* p64 = (const long long*)pix;
    int ok_p = 1;
    for (int i = 0; i < 64; i++) {
        long long v = p64[i];
        if (v < -1 || v >= NUM_FACES) { ok_p = 0; break; }
    }
    g_pix_i64 = ok_p;
}

// ---------------------------------------------------------------------------
// Stage 1: collapse face->vertex indirection into an L2-resident table.
// Only batch 0 of verts_attr matters (reference's faithful replication of the
// missing per-batch pixel offset + zero offset for batch 0).
// ---------------------------------------------------------------------------
__global__ __launch_bounds__(256) void uvr_build_face_table(
        const float* __restrict__ verts,
        const void*  __restrict__ faces) {
    int i = blockIdx.x * blockDim.x + threadIdx.x;   // over F*3
    if (i >= NUM_FACES * 3) return;
    long long v = g_faces_i64 ? ((const long long*)faces)[i]
                              : (long long)((const int*)faces)[i];
    int vi = (int)v;
    vi = (vi < 0) ? 0 : (vi >= NUM_VERTS ? NUM_VERTS - 1 : vi);  // safety clamp
    const float* p = verts + (size_t)vi * 3;
    g_face_attr[i] = make_float4(p[0], p[1], p[2], 0.0f);
}

// ---------------------------------------------------------------------------
// Stage 2: interpolate + 16-way batch broadcast. 4 pixels/thread.
// Streaming stores: output is write-once, keep L2 for the gather table.
// ---------------------------------------------------------------------------
__global__ __launch_bounds__(256) void uvr_render(
        const void*  __restrict__ pixv,   // (H, W) indices
        const float* __restrict__ bary,   // (H, W, 3) f32
        float*       __restrict__ out) {  // (N, H, W, 3) f32
    int t = blockIdx.x * blockDim.x + threadIdx.x;
    int p0 = t * 4;                       // 4 pixels per thread
    if (p0 >= HW) return;

    long long pf[4];
    if (g_pix_i64) {
        longlong2 a = ((const longlong2*)pixv)[t * 2];
        longlong2 b = ((const longlong2*)pixv)[t * 2 + 1];
        pf[0] = a.x; pf[1] = a.y; pf[2] = b.x; pf[3] = b.y;
    } else {
        int4 a = ((const int4*)pixv)[t];
        pf[0] = a.x; pf[1] = a.y; pf[2] = a.z; pf[3] = a.w;
    }

    const float4* bv = reinterpret_cast<const float4*>(bary + (size_t)p0 * 3);
    float4 b0 = bv[0], b1 = bv[1], b2 = bv[2];
    float bc[4][3] = {
        {b0.x, b0.y, b0.z},
        {b0.w, b1.x, b1.y},
        {b1.z, b1.w, b2.x},
        {b2.y, b2.z, b2.w}
    };

    float r[4][3];
#pragma unroll
    for (int i = 0; i < 4; i++) {
        long long f = pf[i];
        float m = (f >= 0) ? 1.0f : 0.0f;
        int idx = (int)f;
        idx = (idx < 0) ? 0 : (idx >= NUM_FACES ? NUM_FACES - 1 : idx);  // clamp
        float4 a0 = g_face_attr[idx * 3 + 0];
        float4 a1 = g_face_attr[idx * 3 + 1];
        float4 a2 = g_face_attr[idx * 3 + 2];
        r[i][0] = m * (bc[i][0] * a0.x + bc[i][1] * a1.x + bc[i][2] * a2.x);
        r[i][1] = m * (bc[i][0] * a0.y + bc[i][1] * a1.y + bc[i][2] * a2.y);
        r[i][2] = m * (bc[i][0] * a0.z + bc[i][1] * a1.z + bc[i][2] * a2.z);
    }

    // Pack 4 pixels * 3 comps = 12 floats into 3 float4 (48 contiguous bytes).
    float4 o0 = make_float4(r[0][0], r[0][1], r[0][2], r[1][0]);
    float4 o1 = make_float4(r[1][1], r[1][2], r[2][0], r[2][1]);
    float4 o2 = make_float4(r[2][2], r[3][0], r[3][1], r[3][2]);

    size_t base = (size_t)p0 * 3;
#pragma unroll
    for (int n = 0; n < NB; n++) {
        float4* op = reinterpret_cast<float4*>(out + (size_t)n * ((size_t)HW * 3) + base);
        __stcs(op + 0, o0);
        __stcs(op + 1, o1);
        __stcs(op + 2, o2);
    }
}

extern "C" void kernel_launch(void* const* d_in, const int* in_sizes, int n_in,
                              void* d_out, int out_size) {
    // Identify inputs by element count (pairwise distinct) — order-proof.
    const float* verts = nullptr;
    const void*  faces = nullptr;
    const void*  pix   = nullptr;
    const float* bary  = nullptr;
    for (int i = 0; i < n_in; i++) {
        switch (in_sizes[i]) {
            case SZ_VERTS: verts = (const float*)d_in[i]; break;
            case SZ_FACES: faces = d_in[i];               break;
            case SZ_PIX:   pix   = d_in[i];               break;
            case SZ_BARY:  bary  = (const float*)d_in[i]; break;
            default: break;
        }
    }
    // Fallback to declared order if size matching failed.
    if (!verts) verts = (const float*)d_in[0];
    if (!faces) faces = d_in[1];
    if (!pix)   pix   = d_in[2];
    if (!bary)  bary  = (const float*)d_in[3];

    float* out = (float*)d_out;
    (void)out_size;

    uvr_probe<<<1, 32>>>(faces, pix);

    {
        int n = NUM_FACES * 3;
        uvr_build_face_table<<<(n + 255) / 256, 256>>>(verts, faces);
    }
    {
        int threads = HW / 4;                 // 262144
        uvr_render<<<threads / 256, 256>>>(pix, bary, out);
    }
}